// round 8
// baseline (speedup 1.0000x reference)
#include <cuda_runtime.h>
#include <cuda_fp16.h>
#include <math.h>

#define N_TOK 2304
#define LOG2E 1.4426950408889634f

// Scratch (device globals: allocation-free per harness rules)
__device__ float g_qkv[2u * 1536u * 2304u];   // (B, 3*512, N)
__device__ float g_inv[2 * 1024];             // inv L2 norms
__device__ float g_att[2u * 512u * 2304u];    // attention output (B, 512, N)
__device__ float g_w1[1536 * 256];            // tf32-rounded w_qkv
__device__ float g_w2[256 * 512];             // tf32-rounded w_proj
__device__ __half g_qh[16u * 2304u * 64u];    // fp16 Q, [bh][token][d], scaled
__device__ __half g_kh[16u * 2304u * 64u];    // fp16 K, [bh][token][d]
__device__ __half g_vh[16u * 64u * 2304u];    // fp16 V, [bh][d][token]

__device__ __forceinline__ float to_tf32(float x) {
    float r;
    asm("cvt.rna.tf32.f32 %0, %1;" : "=f"(r) : "f"(x));
    return r;
}
__device__ __forceinline__ float ex2(float x) {
    float r;
    asm("ex2.approx.f32 %0, %1;" : "=f"(r) : "f"(x));
    return r;
}
__device__ __forceinline__ unsigned fb(float x) { return __float_as_uint(x); }
__device__ __forceinline__ unsigned packh(float lo, float hi) {
    unsigned r;
    asm("cvt.rn.f16x2.f32 %0, %1, %2;" : "=r"(r) : "f"(hi), "f"(lo));
    return r;
}

__device__ __forceinline__ void mma_tf32(float* d, const unsigned* a, const unsigned* b) {
    asm volatile(
        "mma.sync.aligned.m16n8k8.row.col.f32.tf32.tf32.f32 "
        "{%0,%1,%2,%3}, {%4,%5,%6,%7}, {%8,%9}, {%0,%1,%2,%3};\n"
        : "+f"(d[0]), "+f"(d[1]), "+f"(d[2]), "+f"(d[3])
        : "r"(a[0]), "r"(a[1]), "r"(a[2]), "r"(a[3]), "r"(b[0]), "r"(b[1]));
}
__device__ __forceinline__ void mma_f16(float* d, const unsigned* a, const unsigned* b) {
    asm volatile(
        "mma.sync.aligned.m16n8k16.row.col.f32.f16.f16.f32 "
        "{%0,%1,%2,%3}, {%4,%5,%6,%7}, {%8,%9}, {%0,%1,%2,%3};\n"
        : "+f"(d[0]), "+f"(d[1]), "+f"(d[2]), "+f"(d[3])
        : "r"(a[0]), "r"(a[1]), "r"(a[2]), "r"(a[3]), "r"(b[0]), "r"(b[1]));
}

__device__ __forceinline__ void cp16(unsigned dst, const void* src) {
    asm volatile("cp.async.ca.shared.global [%0], [%1], 16;" :: "r"(dst), "l"(src));
}
#define CP_COMMIT asm volatile("cp.async.commit_group;")
#define CP_WAIT(n) asm volatile("cp.async.wait_group %0;" :: "n"(n))

// ---------------------------------------------------------------------------
__global__ void round_w(const float* __restrict__ a, const float* __restrict__ b,
                        float* __restrict__ wa, float* __restrict__ wb,
                        int na, int nb) {
    int i = blockIdx.x * 256 + threadIdx.x;
    if (i < na) wa[i] = to_tf32(a[i]);
    if (i < nb) wb[i] = to_tf32(b[i]);
}

// ---------------------------------------------------------------------------
// tf32 GEMM (unchanged, proven)
// ---------------------------------------------------------------------------
template <int BM, int WM>
__global__ __launch_bounds__(256) void gemm2(
    const float* __restrict__ W, const float* __restrict__ X,
    const float* __restrict__ bias, float* __restrict__ Y, int K, int Mtot) {
    constexpr int NG = WM / 16;
    __shared__ float As[2][BM * 20];
    __shared__ float Bs[2][16 * 136];

    const int tid = threadIdx.x, lane = tid & 31, w = tid >> 5;
    const int g = lane >> 2, tg = lane & 3;
    const int wm0 = (w & 3) * WM, wn0 = (w >> 2) * 64;
    const int n0 = blockIdx.x * 128;
    const int m0 = blockIdx.y * BM;
    const int b  = blockIdx.z;
    const float* Xb = X + (size_t)b * K * N_TOK;
    float* Yb = Y + (size_t)b * Mtot * N_TOK;

    const unsigned sA = (unsigned)__cvta_generic_to_shared(&As[0][0]);
    const unsigned sB = (unsigned)__cvta_generic_to_shared(&Bs[0][0]);

    float acc[NG][8][4] = {};

    auto issue = [&](int k0, int buf) {
#pragma unroll
        for (int e = tid; e < BM * 4; e += 256) {
            int m = e >> 2, kq = e & 3;
            cp16(sA + (buf * BM * 20 + m * 20 + kq * 4) * 4,
                 W + (size_t)(m0 + m) * K + k0 + kq * 4);
        }
#pragma unroll
        for (int e = tid; e < 512; e += 256) {
            int kk = e >> 5, nq = e & 31;
            cp16(sB + (buf * 16 * 136 + kk * 136 + nq * 4) * 4,
                 Xb + (size_t)(k0 + kk) * N_TOK + n0 + nq * 4);
        }
        CP_COMMIT;
    };

    issue(0, 0);
    for (int k0 = 0; k0 < K; k0 += 16) {
        int buf = (k0 >> 4) & 1;
        if (k0 + 16 < K) { issue(k0 + 16, buf ^ 1); CP_WAIT(1); }
        else             { CP_WAIT(0); }
        __syncthreads();
        const float* Ab = As[buf];
        const float* Bb = Bs[buf];
#pragma unroll
        for (int kc = 0; kc < 16; kc += 8) {
            unsigned a[NG][4];
#pragma unroll
            for (int s = 0; s < NG; s++) {
                int r = wm0 + 16 * s + g;
                a[s][0] = fb(Ab[r * 20 + kc + tg]);
                a[s][1] = fb(Ab[(r + 8) * 20 + kc + tg]);
                a[s][2] = fb(Ab[r * 20 + kc + tg + 4]);
                a[s][3] = fb(Ab[(r + 8) * 20 + kc + tg + 4]);
            }
#pragma unroll
            for (int nf = 0; nf < 8; nf++) {
                unsigned bb[2];
                bb[0] = fb(Bb[(kc + tg) * 136 + wn0 + nf * 8 + g]);
                bb[1] = fb(Bb[(kc + tg + 4) * 136 + wn0 + nf * 8 + g]);
#pragma unroll
                for (int s = 0; s < NG; s++) mma_tf32(acc[s][nf], a[s], bb);
            }
        }
        __syncthreads();
    }
#pragma unroll
    for (int s = 0; s < NG; s++) {
        int r0 = m0 + wm0 + 16 * s + g, r1 = r0 + 8;
        float bv0 = bias ? bias[r0] : 0.f;
        float bv1 = bias ? bias[r1] : 0.f;
#pragma unroll
        for (int nf = 0; nf < 8; nf++) {
            *(float2*)(Yb + (size_t)r0 * N_TOK + n0 + wn0 + nf * 8 + tg * 2) =
                make_float2(acc[s][nf][0] + bv0, acc[s][nf][1] + bv0);
            *(float2*)(Yb + (size_t)r1 * N_TOK + n0 + wn0 + nf * 8 + tg * 2) =
                make_float2(acc[s][nf][2] + bv1, acc[s][nf][3] + bv1);
        }
    }
}

// ---------------------------------------------------------------------------
// Row L2-norm inverse
// ---------------------------------------------------------------------------
__global__ void norm_k(const float* __restrict__ qkv, float* __restrict__ inv) {
    const int row = blockIdx.x;
    const int b = row >> 10, o = row & 1023;
    const float* p = qkv + ((size_t)b * 1536 + o) * N_TOK;
    float ss = 0.f;
    for (int i = threadIdx.x; i < N_TOK; i += 256) {
        float v = p[i];
        ss += v * v;
    }
#pragma unroll
    for (int off = 16; off; off >>= 1)
        ss += __shfl_xor_sync(0xffffffffu, ss, off);
    __shared__ float red[8];
    if ((threadIdx.x & 31) == 0) red[threadIdx.x >> 5] = ss;
    __syncthreads();
    if (threadIdx.x == 0) {
        float t = 0.f;
#pragma unroll
        for (int i = 0; i < 8; i++) t += red[i];
        inv[row] = 1.f / fmaxf(sqrtf(t), 1e-12f);
    }
}

// ---------------------------------------------------------------------------
// Convert q,k,v to fp16: Q scaled+transposed [bh][tok][d], K transposed
// [bh][tok][d], V straight [bh][d][tok]. Block = 64 tokens of one (b,h).
// ---------------------------------------------------------------------------
__global__ __launch_bounds__(256) void cvt_qkv(
    const float* __restrict__ qkv, const float* __restrict__ inv,
    __half* __restrict__ qh, __half* __restrict__ kh, __half* __restrict__ vh) {
    __shared__ float F[64 * 67];    // transpose tile, stride 67
    const int tid = threadIdx.x;
    const int t0 = blockIdx.x * 64;
    const int h = blockIdx.y, b = blockIdx.z;
    const int bh = b * 8 + h;
    const float* qsrc = qkv + ((size_t)b * 1536 + h * 64) * N_TOK;
    const float* ksrc = qsrc + (size_t)512 * N_TOK;
    const float* vsrc = qsrc + (size_t)1024 * N_TOK;
    const float* invq = inv + b * 1024 + h * 64;
    const float* invk = invq + 512;

    // V: straight convert (coalesced both sides)
    for (int e = tid; e < 1024; e += 256) {
        int d = e >> 4, m4 = e & 15;
        float4 t = *(const float4*)(vsrc + (size_t)d * N_TOK + t0 + m4 * 4);
        __half2* dst = (__half2*)(vh + ((size_t)bh * 64 + d) * N_TOK + t0 + m4 * 4);
        dst[0] = __floats2half2_rn(t.x, t.y);
        dst[1] = __floats2half2_rn(t.z, t.w);
    }

    // Q: scale + transpose via smem
    for (int e = tid; e < 1024; e += 256) {
        int d = e >> 4, m4 = e & 15;
        float4 t = *(const float4*)(qsrc + (size_t)d * N_TOK + t0 + m4 * 4);
        float s = invq[d] * invk[d] * LOG2E;
        float* p = &F[d * 67 + m4 * 4];
        p[0] = t.x * s; p[1] = t.y * s; p[2] = t.z * s; p[3] = t.w * s;
    }
    __syncthreads();
    for (int e = tid; e < 512; e += 256) {
        int m = e >> 3, c = e & 7;
        __half2 o[4];
#pragma unroll
        for (int j = 0; j < 4; j++)
            o[j] = __floats2half2_rn(F[(8 * c + 2 * j) * 67 + m],
                                     F[(8 * c + 2 * j + 1) * 67 + m]);
        *(uint4*)(qh + ((size_t)bh * N_TOK + t0 + m) * 64 + 8 * c) = *(uint4*)o;
    }
    __syncthreads();

    // K: transpose via smem
    for (int e = tid; e < 1024; e += 256) {
        int d = e >> 4, m4 = e & 15;
        float4 t = *(const float4*)(ksrc + (size_t)d * N_TOK + t0 + m4 * 4);
        float* p = &F[d * 67 + m4 * 4];
        p[0] = t.x; p[1] = t.y; p[2] = t.z; p[3] = t.w;
    }
    __syncthreads();
    for (int e = tid; e < 512; e += 256) {
        int m = e >> 3, c = e & 7;
        __half2 o[4];
#pragma unroll
        for (int j = 0; j < 4; j++)
            o[j] = __floats2half2_rn(F[(8 * c + 2 * j) * 67 + m],
                                     F[(8 * c + 2 * j + 1) * 67 + m]);
        *(uint4*)(kh + ((size_t)bh * N_TOK + t0 + m) * 64 + 8 * c) = *(uint4*)o;
    }
}

// ---------------------------------------------------------------------------
// Flash attention v6: fp16 m16n8k16, 256 queries/block, 8 warps x 32 rows.
// Bounded softmax (no max/rescale), Q frags register-hoisted, 3-stage cp.async.
// Smem: Kt[3][64][72] halves | Vt[3][64][72] halves  (55296 B)
// ---------------------------------------------------------------------------
#define KT_STR 72
#define KV_STAGE (64 * KT_STR)
#define ATTN_SMEM (6 * KV_STAGE * 2)   // 55296 B

__global__ __launch_bounds__(256, 1) void attn6(
    const __half* __restrict__ qh, const __half* __restrict__ kh,
    const __half* __restrict__ vh, float* __restrict__ out) {
    extern __shared__ __half smh[];
    __half* KtBase = smh;
    __half* VtBase = smh + 3 * KV_STAGE;

    const int tid = threadIdx.x, lane = tid & 31, w = tid >> 5;
    const int g = lane >> 2, tg = lane & 3;
    const int n0 = blockIdx.x * 256;
    const int bh = blockIdx.z * 8 + blockIdx.y;
    const int i0 = w * 32;

    const __half* qb = qh + (size_t)bh * N_TOK * 64;
    const __half* kb = kh + (size_t)bh * N_TOK * 64;
    const __half* vb = vh + (size_t)bh * 64 * N_TOK;

    const unsigned sBase = (unsigned)__cvta_generic_to_shared(smh);

    auto issueKV = [&](int t0, int buf) {
#pragma unroll
        for (int e = tid; e < 512; e += 256) {
            int m = e >> 3, c = e & 7;
            cp16(sBase + (buf * KV_STAGE + m * KT_STR + c * 8) * 2,
                 kb + (size_t)(t0 + m) * 64 + c * 8);
            cp16(sBase + ((3 + buf) * KV_STAGE + m * KT_STR + c * 8) * 2,
                 vb + (size_t)m * N_TOK + t0 + c * 8);
        }
        CP_COMMIT;
    };

    issueKV(0, 0);
    issueKV(64, 1);
    issueKV(128, 2);

    // Register-hoist Q fragments (k16: 4 k-steps, 2 row-groups)
    unsigned qa[2][4][4];
#pragma unroll
    for (int grp = 0; grp < 2; grp++) {
#pragma unroll
        for (int kbk = 0; kbk < 4; kbk++) {
            const __half* r0p = qb + (size_t)(n0 + i0 + grp * 16 + g) * 64 + kbk * 16 + 2 * tg;
            const __half* r1p = r0p + 8 * 64;
            qa[grp][kbk][0] = *(const unsigned*)r0p;
            qa[grp][kbk][1] = *(const unsigned*)r1p;
            qa[grp][kbk][2] = *(const unsigned*)(r0p + 8);
            qa[grp][kbk][3] = *(const unsigned*)(r1p + 8);
        }
    }

    float O[2][8][4] = {};
    float l00 = 0.f, l01 = 0.f, l10 = 0.f, l11 = 0.f;

    for (int it = 0; it < 36; it++) {
        int buf = it % 3;
        CP_WAIT(2);
        __syncthreads();
        const __half* Kb = KtBase + buf * KV_STAGE;
        const __half* Vb = VtBase + buf * KV_STAGE;

        // S-phase: S(32x64) = Q x K^T, k16 steps over d
        float S[2][8][4] = {};
#pragma unroll
        for (int kbk = 0; kbk < 4; kbk++) {
#pragma unroll
            for (int nf = 0; nf < 8; nf++) {
                const __half* kp = Kb + (nf * 8 + g) * KT_STR + kbk * 16 + 2 * tg;
                unsigned bb[2];
                bb[0] = *(const unsigned*)kp;
                bb[1] = *(const unsigned*)(kp + 8);
                mma_f16(S[0][nf], qa[0][kbk], bb);
                mma_f16(S[1][nf], qa[1][kbk], bb);
            }
        }

        // Bounded softmax: P = exp2(S) (log2e pre-folded), deferred l
#pragma unroll
        for (int nf = 0; nf < 8; nf++) {
            S[0][nf][0] = ex2(S[0][nf][0]); S[0][nf][1] = ex2(S[0][nf][1]);
            S[0][nf][2] = ex2(S[0][nf][2]); S[0][nf][3] = ex2(S[0][nf][3]);
            S[1][nf][0] = ex2(S[1][nf][0]); S[1][nf][1] = ex2(S[1][nf][1]);
            S[1][nf][2] = ex2(S[1][nf][2]); S[1][nf][3] = ex2(S[1][nf][3]);
            l00 += S[0][nf][0] + S[0][nf][1];
            l01 += S[0][nf][2] + S[0][nf][3];
            l10 += S[1][nf][0] + S[1][nf][1];
            l11 += S[1][nf][2] + S[1][nf][3];
        }

        // PV-phase: A = P (fp16 pack; k16 A-frag == two adjacent S blocks)
#pragma unroll
        for (int kk = 0; kk < 4; kk++) {
            unsigned pa0[4], pa1[4];
            pa0[0] = packh(S[0][2 * kk][0], S[0][2 * kk][1]);
            pa0[1] = packh(S[0][2 * kk][2], S[0][2 * kk][3]);
            pa0[2] = packh(S[0][2 * kk + 1][0], S[0][2 * kk + 1][1]);
            pa0[3] = packh(S[0][2 * kk + 1][2], S[0][2 * kk + 1][3]);
            pa1[0] = packh(S[1][2 * kk][0], S[1][2 * kk][1]);
            pa1[1] = packh(S[1][2 * kk][2], S[1][2 * kk][3]);
            pa1[2] = packh(S[1][2 * kk + 1][0], S[1][2 * kk + 1][1]);
            pa1[3] = packh(S[1][2 * kk + 1][2], S[1][2 * kk + 1][3]);
#pragma unroll
            for (int nf = 0; nf < 8; nf++) {
                const __half* vp = Vb + (nf * 8 + g) * KT_STR + kk * 16 + 2 * tg;
                unsigned bb[2];
                bb[0] = *(const unsigned*)vp;
                bb[1] = *(const unsigned*)(vp + 8);
                mma_f16(O[0][nf], pa0, bb);
                mma_f16(O[1][nf], pa1, bb);
            }
        }
        __syncthreads();
        if (it + 3 < 36) issueKV((it + 3) * 64, buf);
        else             CP_COMMIT;    // empty group keeps wait arithmetic uniform
    }

    // Deferred l-reduction over the 4 tg-lanes per row
    l00 += __shfl_xor_sync(0xffffffffu, l00, 1);
    l00 += __shfl_xor_sync(0xffffffffu, l00, 2);
    l01 += __shfl_xor_sync(0xffffffffu, l01, 1);
    l01 += __shfl_xor_sync(0xffffffffu, l01, 2);
    l10 += __shfl_xor_sync(0xffffffffu, l10, 1);
    l10 += __shfl_xor_sync(0xffffffffu, l10, 2);
    l11 += __shfl_xor_sync(0xffffffffu, l11, 1);
    l11 += __shfl_xor_sync(0xffffffffu, l11, 2);
    float rl[2][2] = {{1.f / l00, 1.f / l01}, {1.f / l10, 1.f / l11}};

    // Epilogue: stage d-major via smem (alias KV region), write fp32
    float* Os = (float*)smh;   // 64 x 136 floats = 34.8 KB < 55.3 KB
    float* ob = out + (size_t)bh * 512 / 8 * 8 * N_TOK;  // bh*512? no:
    ob = out + ((size_t)blockIdx.z * 512 + blockIdx.y * 64) * N_TOK;
#pragma unroll
    for (int pass = 0; pass < 2; pass++) {
        __syncthreads();
        if ((w >> 2) == pass) {
            int base = (w & 3) * 32;
#pragma unroll
            for (int grp = 0; grp < 2; grp++) {
                int ir0 = base + 16 * grp + g, ir1 = ir0 + 8;
#pragma unroll
                for (int nf = 0; nf < 8; nf++) {
                    int d0 = nf * 8 + 2 * tg;
                    Os[d0 * 136 + ir0]       = O[grp][nf][0] * rl[grp][0];
                    Os[(d0 + 1) * 136 + ir0] = O[grp][nf][1] * rl[grp][0];
                    Os[d0 * 136 + ir1]       = O[grp][nf][2] * rl[grp][1];
                    Os[(d0 + 1) * 136 + ir1] = O[grp][nf][3] * rl[grp][1];
                }
            }
        }
        __syncthreads();
        for (int e = tid; e < 2048; e += 256) {
            int d = e >> 5, i4 = e & 31;
            float4 t = *(const float4*)(&Os[d * 136 + i4 * 4]);
            *(float4*)(ob + (size_t)d * N_TOK + n0 + pass * 128 + i4 * 4) = t;
        }
    }
}

// ---------------------------------------------------------------------------
extern "C" void kernel_launch(void* const* d_in, const int* in_sizes, int n_in,
                              void* d_out, int out_size) {
    (void)in_sizes; (void)n_in; (void)out_size;
    const float* x      = (const float*)d_in[0];
    const float* w_qkv  = (const float*)d_in[1];
    const float* w_proj = (const float*)d_in[2];
    const float* b_proj = (const float*)d_in[3];
    float* y = (float*)d_out;

    float *qkv_p, *inv_p, *att_p, *w1_p, *w2_p;
    __half *qh_p, *kh_p, *vh_p;
    cudaGetSymbolAddress((void**)&qkv_p, g_qkv);
    cudaGetSymbolAddress((void**)&inv_p, g_inv);
    cudaGetSymbolAddress((void**)&att_p, g_att);
    cudaGetSymbolAddress((void**)&w1_p, g_w1);
    cudaGetSymbolAddress((void**)&w2_p, g_w2);
    cudaGetSymbolAddress((void**)&qh_p, g_qh);
    cudaGetSymbolAddress((void**)&kh_p, g_kh);
    cudaGetSymbolAddress((void**)&vh_p, g_vh);

    cudaFuncSetAttribute(attn6, cudaFuncAttributeMaxDynamicSharedMemorySize,
                         ATTN_SMEM);

    // 0) pre-round weights to tf32
    round_w<<<1536, 256>>>(w_qkv, w_proj, w1_p, w2_p, 1536 * 256, 256 * 512);
    // 1) qkv = w_qkv @ x
    gemm2<128, 32><<<dim3(18, 12, 2), 256>>>(w1_p, x, nullptr, qkv_p, 256, 1536);
    // 2) inverse L2 norms
    norm_k<<<2048, 256>>>(qkv_p, inv_p);
    // 3) convert to fp16 layouts
    cvt_qkv<<<dim3(36, 8, 2), 256>>>(qkv_p, inv_p, qh_p, kh_p, vh_p);
    // 4) flash attention fp16
    attn6<<<dim3(9, 8, 2), 256, ATTN_SMEM>>>(qh_p, kh_p, vh_p, att_p);
    // 5) y = w_proj @ att + b_proj
    gemm2<64, 16><<<dim3(18, 4, 2), 256>>>(w2_p, att_p, b_proj, y, 512, 256);
}

// round 9
// speedup vs baseline: 1.6032x; 1.6032x over previous
#include <cuda_runtime.h>
#include <cuda_fp16.h>
#include <math.h>

#define N_TOK 2304
#define LOG2E 1.4426950408889634f

// Scratch (device globals: allocation-free per harness rules)
__device__ float g_qkv[2u * 1536u * 2304u];   // (B, 3*512, N)
__device__ float g_inv[2 * 1024];             // inv L2 norms
__device__ float g_att[2u * 512u * 2304u];    // attention output (B, 512, N)
__device__ float g_w1[1536 * 256];            // tf32-rounded w_qkv
__device__ float g_w2[256 * 512];             // tf32-rounded w_proj
__device__ __half g_qh[16u * 2304u * 64u];    // fp16 Q, [bh][token][d], scaled
__device__ __half g_kh[16u * 2304u * 64u];    // fp16 K, [bh][token][d]
__device__ __half g_vh[16u * 64u * 2304u];    // fp16 V, [bh][d][token]

__device__ __forceinline__ float to_tf32(float x) {
    float r;
    asm("cvt.rna.tf32.f32 %0, %1;" : "=f"(r) : "f"(x));
    return r;
}
__device__ __forceinline__ unsigned fb(float x) { return __float_as_uint(x); }

__device__ __forceinline__ void mma_tf32(float* d, const unsigned* a, const unsigned* b) {
    asm volatile(
        "mma.sync.aligned.m16n8k8.row.col.f32.tf32.tf32.f32 "
        "{%0,%1,%2,%3}, {%4,%5,%6,%7}, {%8,%9}, {%0,%1,%2,%3};\n"
        : "+f"(d[0]), "+f"(d[1]), "+f"(d[2]), "+f"(d[3])
        : "r"(a[0]), "r"(a[1]), "r"(a[2]), "r"(a[3]), "r"(b[0]), "r"(b[1]));
}
// fp16 inputs, fp32 accumulator
__device__ __forceinline__ void mma_f16(float* d, const unsigned* a, const unsigned* b) {
    asm volatile(
        "mma.sync.aligned.m16n8k16.row.col.f32.f16.f16.f32 "
        "{%0,%1,%2,%3}, {%4,%5,%6,%7}, {%8,%9}, {%0,%1,%2,%3};\n"
        : "+f"(d[0]), "+f"(d[1]), "+f"(d[2]), "+f"(d[3])
        : "r"(a[0]), "r"(a[1]), "r"(a[2]), "r"(a[3]), "r"(b[0]), "r"(b[1]));
}
// fp16 inputs, fp16 accumulator (for S)
__device__ __forceinline__ void mma_f16acc(unsigned* d, const unsigned* a, const unsigned* b) {
    asm volatile(
        "mma.sync.aligned.m16n8k16.row.col.f16.f16.f16.f16 "
        "{%0,%1}, {%2,%3,%4,%5}, {%6,%7}, {%0,%1};\n"
        : "+r"(d[0]), "+r"(d[1])
        : "r"(a[0]), "r"(a[1]), "r"(a[2]), "r"(a[3]), "r"(b[0]), "r"(b[1]));
}
__device__ __forceinline__ void ldsm4(unsigned* r, unsigned addr) {
    asm volatile("ldmatrix.sync.aligned.m8n8.x4.shared.b16 {%0,%1,%2,%3}, [%4];"
                 : "=r"(r[0]), "=r"(r[1]), "=r"(r[2]), "=r"(r[3]) : "r"(addr));
}
__device__ __forceinline__ unsigned ex2h2(unsigned x) {
    unsigned r;
    asm("ex2.approx.f16x2 %0, %1;" : "=r"(r) : "r"(x));
    return r;
}

__device__ __forceinline__ void cp16(unsigned dst, const void* src) {
    asm volatile("cp.async.ca.shared.global [%0], [%1], 16;" :: "r"(dst), "l"(src));
}
#define CP_COMMIT asm volatile("cp.async.commit_group;")
#define CP_WAIT(n) asm volatile("cp.async.wait_group %0;" :: "n"(n))

// ---------------------------------------------------------------------------
__global__ void round_w(const float* __restrict__ a, const float* __restrict__ b,
                        float* __restrict__ wa, float* __restrict__ wb,
                        int na, int nb) {
    int i = blockIdx.x * 256 + threadIdx.x;
    if (i < na) wa[i] = to_tf32(a[i]);
    if (i < nb) wb[i] = to_tf32(b[i]);
}

// ---------------------------------------------------------------------------
// tf32 GEMM (unchanged, proven)
// ---------------------------------------------------------------------------
template <int BM, int WM>
__global__ __launch_bounds__(256) void gemm2(
    const float* __restrict__ W, const float* __restrict__ X,
    const float* __restrict__ bias, float* __restrict__ Y, int K, int Mtot) {
    constexpr int NG = WM / 16;
    __shared__ float As[2][BM * 20];
    __shared__ float Bs[2][16 * 136];

    const int tid = threadIdx.x, lane = tid & 31, w = tid >> 5;
    const int g = lane >> 2, tg = lane & 3;
    const int wm0 = (w & 3) * WM, wn0 = (w >> 2) * 64;
    const int n0 = blockIdx.x * 128;
    const int m0 = blockIdx.y * BM;
    const int b  = blockIdx.z;
    const float* Xb = X + (size_t)b * K * N_TOK;
    float* Yb = Y + (size_t)b * Mtot * N_TOK;

    const unsigned sA = (unsigned)__cvta_generic_to_shared(&As[0][0]);
    const unsigned sB = (unsigned)__cvta_generic_to_shared(&Bs[0][0]);

    float acc[NG][8][4] = {};

    auto issue = [&](int k0, int buf) {
#pragma unroll
        for (int e = tid; e < BM * 4; e += 256) {
            int m = e >> 2, kq = e & 3;
            cp16(sA + (buf * BM * 20 + m * 20 + kq * 4) * 4,
                 W + (size_t)(m0 + m) * K + k0 + kq * 4);
        }
#pragma unroll
        for (int e = tid; e < 512; e += 256) {
            int kk = e >> 5, nq = e & 31;
            cp16(sB + (buf * 16 * 136 + kk * 136 + nq * 4) * 4,
                 Xb + (size_t)(k0 + kk) * N_TOK + n0 + nq * 4);
        }
        CP_COMMIT;
    };

    issue(0, 0);
    for (int k0 = 0; k0 < K; k0 += 16) {
        int buf = (k0 >> 4) & 1;
        if (k0 + 16 < K) { issue(k0 + 16, buf ^ 1); CP_WAIT(1); }
        else             { CP_WAIT(0); }
        __syncthreads();
        const float* Ab = As[buf];
        const float* Bb = Bs[buf];
#pragma unroll
        for (int kc = 0; kc < 16; kc += 8) {
            unsigned a[NG][4];
#pragma unroll
            for (int s = 0; s < NG; s++) {
                int r = wm0 + 16 * s + g;
                a[s][0] = fb(Ab[r * 20 + kc + tg]);
                a[s][1] = fb(Ab[(r + 8) * 20 + kc + tg]);
                a[s][2] = fb(Ab[r * 20 + kc + tg + 4]);
                a[s][3] = fb(Ab[(r + 8) * 20 + kc + tg + 4]);
            }
#pragma unroll
            for (int nf = 0; nf < 8; nf++) {
                unsigned bb[2];
                bb[0] = fb(Bb[(kc + tg) * 136 + wn0 + nf * 8 + g]);
                bb[1] = fb(Bb[(kc + tg + 4) * 136 + wn0 + nf * 8 + g]);
#pragma unroll
                for (int s = 0; s < NG; s++) mma_tf32(acc[s][nf], a[s], bb);
            }
        }
        __syncthreads();
    }
#pragma unroll
    for (int s = 0; s < NG; s++) {
        int r0 = m0 + wm0 + 16 * s + g, r1 = r0 + 8;
        float bv0 = bias ? bias[r0] : 0.f;
        float bv1 = bias ? bias[r1] : 0.f;
#pragma unroll
        for (int nf = 0; nf < 8; nf++) {
            *(float2*)(Yb + (size_t)r0 * N_TOK + n0 + wn0 + nf * 8 + tg * 2) =
                make_float2(acc[s][nf][0] + bv0, acc[s][nf][1] + bv0);
            *(float2*)(Yb + (size_t)r1 * N_TOK + n0 + wn0 + nf * 8 + tg * 2) =
                make_float2(acc[s][nf][2] + bv1, acc[s][nf][3] + bv1);
        }
    }
}

// ---------------------------------------------------------------------------
// Row L2-norm inverse
// ---------------------------------------------------------------------------
__global__ void norm_k(const float* __restrict__ qkv, float* __restrict__ inv) {
    const int row = blockIdx.x;
    const int b = row >> 10, o = row & 1023;
    const float* p = qkv + ((size_t)b * 1536 + o) * N_TOK;
    float ss = 0.f;
    for (int i = threadIdx.x; i < N_TOK; i += 256) {
        float v = p[i];
        ss += v * v;
    }
#pragma unroll
    for (int off = 16; off; off >>= 1)
        ss += __shfl_xor_sync(0xffffffffu, ss, off);
    __shared__ float red[8];
    if ((threadIdx.x & 31) == 0) red[threadIdx.x >> 5] = ss;
    __syncthreads();
    if (threadIdx.x == 0) {
        float t = 0.f;
#pragma unroll
        for (int i = 0; i < 8; i++) t += red[i];
        inv[row] = 1.f / fmaxf(sqrtf(t), 1e-12f);
    }
}

// ---------------------------------------------------------------------------
// Convert q,k,v to fp16 (unchanged from round 7)
// ---------------------------------------------------------------------------
__global__ __launch_bounds__(256) void cvt_qkv(
    const float* __restrict__ qkv, const float* __restrict__ inv,
    __half* __restrict__ qh, __half* __restrict__ kh, __half* __restrict__ vh) {
    __shared__ float F[64 * 67];
    const int tid = threadIdx.x;
    const int t0 = blockIdx.x * 64;
    const int h = blockIdx.y, b = blockIdx.z;
    const int bh = b * 8 + h;
    const float* qsrc = qkv + ((size_t)b * 1536 + h * 64) * N_TOK;
    const float* ksrc = qsrc + (size_t)512 * N_TOK;
    const float* vsrc = qsrc + (size_t)1024 * N_TOK;
    const float* invq = inv + b * 1024 + h * 64;
    const float* invk = invq + 512;

    for (int e = tid; e < 1024; e += 256) {
        int d = e >> 4, m4 = e & 15;
        float4 t = *(const float4*)(vsrc + (size_t)d * N_TOK + t0 + m4 * 4);
        __half2* dst = (__half2*)(vh + ((size_t)bh * 64 + d) * N_TOK + t0 + m4 * 4);
        dst[0] = __floats2half2_rn(t.x, t.y);
        dst[1] = __floats2half2_rn(t.z, t.w);
    }

    for (int e = tid; e < 1024; e += 256) {
        int d = e >> 4, m4 = e & 15;
        float4 t = *(const float4*)(qsrc + (size_t)d * N_TOK + t0 + m4 * 4);
        float s = invq[d] * invk[d] * LOG2E;
        float* p = &F[d * 67 + m4 * 4];
        p[0] = t.x * s; p[1] = t.y * s; p[2] = t.z * s; p[3] = t.w * s;
    }
    __syncthreads();
    for (int e = tid; e < 512; e += 256) {
        int m = e >> 3, c = e & 7;
        __half2 o[4];
#pragma unroll
        for (int j = 0; j < 4; j++)
            o[j] = __floats2half2_rn(F[(8 * c + 2 * j) * 67 + m],
                                     F[(8 * c + 2 * j + 1) * 67 + m]);
        *(uint4*)(qh + ((size_t)bh * N_TOK + t0 + m) * 64 + 8 * c) = *(uint4*)o;
    }
    __syncthreads();

    for (int e = tid; e < 1024; e += 256) {
        int d = e >> 4, m4 = e & 15;
        float4 t = *(const float4*)(ksrc + (size_t)d * N_TOK + t0 + m4 * 4);
        float* p = &F[d * 67 + m4 * 4];
        p[0] = t.x; p[1] = t.y; p[2] = t.z; p[3] = t.w;
    }
    __syncthreads();
    for (int e = tid; e < 512; e += 256) {
        int m = e >> 3, c = e & 7;
        __half2 o[4];
#pragma unroll
        for (int j = 0; j < 4; j++)
            o[j] = __floats2half2_rn(F[(8 * c + 2 * j) * 67 + m],
                                     F[(8 * c + 2 * j + 1) * 67 + m]);
        *(uint4*)(kh + ((size_t)bh * N_TOK + t0 + m) * 64 + 8 * c) = *(uint4*)o;
    }
}

// ---------------------------------------------------------------------------
// Flash attention v7: fp16 m16n8k16, ldmatrix fragments, f16-accumulated S.
// 256 queries/block, 8 warps x 32 rows, bounded softmax, 3-stage cp.async.
// Smem: Kt[3][64][72] halves | Vt[3][64][72] halves  (55296 B)
// ---------------------------------------------------------------------------
#define KT_STR 72
#define KV_STAGE (64 * KT_STR)          // halves per stage
#define ATTN_SMEM (6 * KV_STAGE * 2)    // 55296 B

__global__ __launch_bounds__(256, 1) void attn7(
    const __half* __restrict__ qh, const __half* __restrict__ kh,
    const __half* __restrict__ vh, float* __restrict__ out) {
    extern __shared__ __half smh[];

    const int tid = threadIdx.x, lane = tid & 31, w = tid >> 5;
    const int g = lane >> 2, tg = lane & 3;
    const int n0 = blockIdx.x * 256;
    const int bh = blockIdx.z * 8 + blockIdx.y;
    const int i0 = w * 32;

    const __half* qb = qh + (size_t)bh * N_TOK * 64;
    const __half* kb = kh + (size_t)bh * N_TOK * 64;
    const __half* vb = vh + (size_t)bh * 64 * N_TOK;

    const unsigned sBase = (unsigned)__cvta_generic_to_shared(smh);
    // ldmatrix per-lane offset (bytes): row (lane&7), tile-pair row +8 for
    // lanes 16-31, d/tok +8 for tiles 1,3 (lanes 8-15, 24-31)
    const unsigned lp = (((lane & 7) + ((lane >> 4) & 1) * 8) * KT_STR +
                         ((lane >> 3) & 1) * 8) * 2;

    auto issueKV = [&](int t0, int buf) {
#pragma unroll
        for (int e = tid; e < 512; e += 256) {
            int m = e >> 3, c = e & 7;
            cp16(sBase + (buf * KV_STAGE + m * KT_STR + c * 8) * 2,
                 kb + (size_t)(t0 + m) * 64 + c * 8);
            cp16(sBase + ((3 + buf) * KV_STAGE + m * KT_STR + c * 8) * 2,
                 vb + (size_t)m * N_TOK + t0 + c * 8);
        }
        CP_COMMIT;
    };

    issueKV(0, 0);
    issueKV(64, 1);
    issueKV(128, 2);

    // Register-hoist Q fragments (k16: 4 k-steps, 2 row-groups)
    unsigned qa[2][4][4];
#pragma unroll
    for (int grp = 0; grp < 2; grp++) {
#pragma unroll
        for (int kbk = 0; kbk < 4; kbk++) {
            const __half* r0p = qb + (size_t)(n0 + i0 + grp * 16 + g) * 64 + kbk * 16 + 2 * tg;
            const __half* r1p = r0p + 8 * 64;
            qa[grp][kbk][0] = *(const unsigned*)r0p;
            qa[grp][kbk][1] = *(const unsigned*)r1p;
            qa[grp][kbk][2] = *(const unsigned*)(r0p + 8);
            qa[grp][kbk][3] = *(const unsigned*)(r1p + 8);
        }
    }

    float O[2][8][4] = {};
    float l00 = 0.f, l01 = 0.f, l10 = 0.f, l11 = 0.f;

    for (int it = 0; it < 36; it++) {
        int buf = it % 3;
        CP_WAIT(2);
        __syncthreads();
        const unsigned kA = sBase + buf * KV_STAGE * 2 + lp;
        const unsigned vA = sBase + (3 + buf) * KV_STAGE * 2 + lp;

        // S-phase: f16-accumulated S(32x64)
        unsigned S16[2][8][2];
#pragma unroll
        for (int grp = 0; grp < 2; grp++)
#pragma unroll
            for (int nf = 0; nf < 8; nf++) {
                S16[grp][nf][0] = 0u; S16[grp][nf][1] = 0u;
            }
#pragma unroll
        for (int kbk = 0; kbk < 4; kbk++) {
            unsigned kr[4][4];
#pragma unroll
            for (int q = 0; q < 4; q++)
                ldsm4(kr[q], kA + (q * 16 * KT_STR + kbk * 16) * 2);
#pragma unroll
            for (int q = 0; q < 4; q++) {
                mma_f16acc(S16[0][2 * q],     qa[0][kbk], &kr[q][0]);
                mma_f16acc(S16[0][2 * q + 1], qa[0][kbk], &kr[q][2]);
                mma_f16acc(S16[1][2 * q],     qa[1][kbk], &kr[q][0]);
                mma_f16acc(S16[1][2 * q + 1], qa[1][kbk], &kr[q][2]);
            }
        }

        // Bounded softmax: P = exp2(S) in f16x2 (log2e pre-folded), exact f32 l
#pragma unroll
        for (int grp = 0; grp < 2; grp++)
#pragma unroll
            for (int nf = 0; nf < 8; nf++) {
                S16[grp][nf][0] = ex2h2(S16[grp][nf][0]);
                S16[grp][nf][1] = ex2h2(S16[grp][nf][1]);
            }
#pragma unroll
        for (int nf = 0; nf < 8; nf++) {
            float2 f;
            f = __half22float2(*(__half2*)&S16[0][nf][0]); l00 += f.x + f.y;
            f = __half22float2(*(__half2*)&S16[0][nf][1]); l01 += f.x + f.y;
            f = __half22float2(*(__half2*)&S16[1][nf][0]); l10 += f.x + f.y;
            f = __half22float2(*(__half2*)&S16[1][nf][1]); l11 += f.x + f.y;
        }

        // PV-phase: A = P (f16 S-accumulator layout == k16 A-fragment layout)
#pragma unroll
        for (int kk = 0; kk < 4; kk++) {
            unsigned vr[4][4];
#pragma unroll
            for (int q = 0; q < 4; q++)
                ldsm4(vr[q], vA + (q * 16 * KT_STR + kk * 16) * 2);
            unsigned pa0[4] = {S16[0][2 * kk][0], S16[0][2 * kk][1],
                              S16[0][2 * kk + 1][0], S16[0][2 * kk + 1][1]};
            unsigned pa1[4] = {S16[1][2 * kk][0], S16[1][2 * kk][1],
                              S16[1][2 * kk + 1][0], S16[1][2 * kk + 1][1]};
#pragma unroll
            for (int q = 0; q < 4; q++) {
                mma_f16(O[0][2 * q],     pa0, &vr[q][0]);
                mma_f16(O[0][2 * q + 1], pa0, &vr[q][2]);
                mma_f16(O[1][2 * q],     pa1, &vr[q][0]);
                mma_f16(O[1][2 * q + 1], pa1, &vr[q][2]);
            }
        }
        __syncthreads();
        if (it + 3 < 36) issueKV((it + 3) * 64, buf);
        else             CP_COMMIT;   // empty group keeps wait arithmetic uniform
    }

    // Deferred l-reduction over the 4 tg-lanes per row
    l00 += __shfl_xor_sync(0xffffffffu, l00, 1);
    l00 += __shfl_xor_sync(0xffffffffu, l00, 2);
    l01 += __shfl_xor_sync(0xffffffffu, l01, 1);
    l01 += __shfl_xor_sync(0xffffffffu, l01, 2);
    l10 += __shfl_xor_sync(0xffffffffu, l10, 1);
    l10 += __shfl_xor_sync(0xffffffffu, l10, 2);
    l11 += __shfl_xor_sync(0xffffffffu, l11, 1);
    l11 += __shfl_xor_sync(0xffffffffu, l11, 2);
    float rl[2][2] = {{1.f / l00, 1.f / l01}, {1.f / l10, 1.f / l11}};

    // Epilogue: stage d-major via smem (alias KV region), write fp32
    float* Os = (float*)smh;   // 64 x 136 floats = 34.8 KB < 55.3 KB
    float* ob = out + ((size_t)blockIdx.z * 512 + blockIdx.y * 64) * N_TOK;
#pragma unroll
    for (int pass = 0; pass < 2; pass++) {
        __syncthreads();
        if ((w >> 2) == pass) {
            int base = (w & 3) * 32;
#pragma unroll
            for (int grp = 0; grp < 2; grp++) {
                int ir0 = base + 16 * grp + g, ir1 = ir0 + 8;
#pragma unroll
                for (int nf = 0; nf < 8; nf++) {
                    int d0 = nf * 8 + 2 * tg;
                    Os[d0 * 136 + ir0]       = O[grp][nf][0] * rl[grp][0];
                    Os[(d0 + 1) * 136 + ir0] = O[grp][nf][1] * rl[grp][0];
                    Os[d0 * 136 + ir1]       = O[grp][nf][2] * rl[grp][1];
                    Os[(d0 + 1) * 136 + ir1] = O[grp][nf][3] * rl[grp][1];
                }
            }
        }
        __syncthreads();
        for (int e = tid; e < 2048; e += 256) {
            int d = e >> 5, i4 = e & 31;
            float4 t = *(const float4*)(&Os[d * 136 + i4 * 4]);
            *(float4*)(ob + (size_t)d * N_TOK + n0 + pass * 128 + i4 * 4) = t;
        }
    }
}

// ---------------------------------------------------------------------------
extern "C" void kernel_launch(void* const* d_in, const int* in_sizes, int n_in,
                              void* d_out, int out_size) {
    (void)in_sizes; (void)n_in; (void)out_size;
    const float* x      = (const float*)d_in[0];
    const float* w_qkv  = (const float*)d_in[1];
    const float* w_proj = (const float*)d_in[2];
    const float* b_proj = (const float*)d_in[3];
    float* y = (float*)d_out;

    float *qkv_p, *inv_p, *att_p, *w1_p, *w2_p;
    __half *qh_p, *kh_p, *vh_p;
    cudaGetSymbolAddress((void**)&qkv_p, g_qkv);
    cudaGetSymbolAddress((void**)&inv_p, g_inv);
    cudaGetSymbolAddress((void**)&att_p, g_att);
    cudaGetSymbolAddress((void**)&w1_p, g_w1);
    cudaGetSymbolAddress((void**)&w2_p, g_w2);
    cudaGetSymbolAddress((void**)&qh_p, g_qh);
    cudaGetSymbolAddress((void**)&kh_p, g_kh);
    cudaGetSymbolAddress((void**)&vh_p, g_vh);

    cudaFuncSetAttribute(attn7, cudaFuncAttributeMaxDynamicSharedMemorySize,
                         ATTN_SMEM);

    // 0) pre-round weights to tf32
    round_w<<<1536, 256>>>(w_qkv, w_proj, w1_p, w2_p, 1536 * 256, 256 * 512);
    // 1) qkv = w_qkv @ x
    gemm2<128, 32><<<dim3(18, 12, 2), 256>>>(w1_p, x, nullptr, qkv_p, 256, 1536);
    // 2) inverse L2 norms
    norm_k<<<2048, 256>>>(qkv_p, inv_p);
    // 3) convert to fp16 layouts
    cvt_qkv<<<dim3(36, 8, 2), 256>>>(qkv_p, inv_p, qh_p, kh_p, vh_p);
    // 4) flash attention fp16 + ldmatrix
    attn7<<<dim3(9, 8, 2), 256, ATTN_SMEM>>>(qh_p, kh_p, vh_p, att_p);
    // 5) y = w_proj @ att + b_proj
    gemm2<64, 16><<<dim3(18, 4, 2), 256>>>(w2_p, att_p, b_proj, y, 512, 256);
}

// round 10
// speedup vs baseline: 1.8956x; 1.1824x over previous
#include <cuda_runtime.h>
#include <cuda_fp16.h>
#include <math.h>

#define N_TOK 2304
#define LOG2E 1.4426950408889634f

// Scratch (device globals: allocation-free per harness rules)
__device__ float  g_qkv[2u * 1536u * 2304u];   // (B, 3*512, N) fp32
__device__ float  g_inv[2 * 1024];             // inv L2 norms
__device__ __half g_xh[2u * 256u * 2304u];     // fp16 x
__device__ __half g_w1h[1536 * 256];           // fp16 w_qkv
__device__ __half g_w2h[256 * 512];            // fp16 w_proj
__device__ __half g_qh[16u * 2304u * 64u];     // fp16 Q, [bh][token][d], scaled
__device__ __half g_kh[16u * 2304u * 64u];     // fp16 K, [bh][token][d]
__device__ __half g_vh[16u * 64u * 2304u];     // fp16 V, [bh][d][token]
__device__ __half g_atth[2u * 512u * 2304u];   // fp16 attention output

__device__ __forceinline__ unsigned fb(float x) { return __float_as_uint(x); }

// fp16 inputs, fp32 accumulator
__device__ __forceinline__ void mma_f16(float* d, const unsigned* a, const unsigned* b) {
    asm volatile(
        "mma.sync.aligned.m16n8k16.row.col.f32.f16.f16.f32 "
        "{%0,%1,%2,%3}, {%4,%5,%6,%7}, {%8,%9}, {%0,%1,%2,%3};\n"
        : "+f"(d[0]), "+f"(d[1]), "+f"(d[2]), "+f"(d[3])
        : "r"(a[0]), "r"(a[1]), "r"(a[2]), "r"(a[3]), "r"(b[0]), "r"(b[1]));
}
// fp16 inputs, fp16 accumulator (for S)
__device__ __forceinline__ void mma_f16acc(unsigned* d, const unsigned* a, const unsigned* b) {
    asm volatile(
        "mma.sync.aligned.m16n8k16.row.col.f16.f16.f16.f16 "
        "{%0,%1}, {%2,%3,%4,%5}, {%6,%7}, {%0,%1};\n"
        : "+r"(d[0]), "+r"(d[1])
        : "r"(a[0]), "r"(a[1]), "r"(a[2]), "r"(a[3]), "r"(b[0]), "r"(b[1]));
}
__device__ __forceinline__ void ldsm4(unsigned* r, unsigned addr) {
    asm volatile("ldmatrix.sync.aligned.m8n8.x4.shared.b16 {%0,%1,%2,%3}, [%4];"
                 : "=r"(r[0]), "=r"(r[1]), "=r"(r[2]), "=r"(r[3]) : "r"(addr));
}
__device__ __forceinline__ void ldsm4t(unsigned* r, unsigned addr) {
    asm volatile("ldmatrix.sync.aligned.m8n8.x4.trans.shared.b16 {%0,%1,%2,%3}, [%4];"
                 : "=r"(r[0]), "=r"(r[1]), "=r"(r[2]), "=r"(r[3]) : "r"(addr));
}
__device__ __forceinline__ unsigned ex2h2(unsigned x) {
    unsigned r;
    asm("ex2.approx.f16x2 %0, %1;" : "=r"(r) : "r"(x));
    return r;
}
__device__ __forceinline__ void cp16(unsigned dst, const void* src) {
    asm volatile("cp.async.ca.shared.global [%0], [%1], 16;" :: "r"(dst), "l"(src));
}
#define CP_COMMIT asm volatile("cp.async.commit_group;")
#define CP_WAIT(n) asm volatile("cp.async.wait_group %0;" :: "n"(n))

// ---------------------------------------------------------------------------
// One-shot input conversion to fp16 (rn)
// ---------------------------------------------------------------------------
__global__ void cvt_in(const float* __restrict__ x, const float* __restrict__ w1,
                       const float* __restrict__ w2, __half* __restrict__ xh,
                       __half* __restrict__ w1h, __half* __restrict__ w2h) {
    int i = blockIdx.x * 256 + threadIdx.x;
    if (i < 2 * 256 * 2304) xh[i] = __float2half_rn(x[i]);
    if (i < 1536 * 256)     w1h[i] = __float2half_rn(w1[i]);
    if (i < 256 * 512)      w2h[i] = __float2half_rn(w2[i]);
}

// ---------------------------------------------------------------------------
// fp16 GEMM: Y[b][m][n] = sum_k W[m][k]*X[b][k][n] (+bias[m]), f32 accum.
// Block BM x 128, 8 warps (4m x 2n), warp WM x 64, k-chunk 32, cp.async x2,
// ldmatrix A (non-trans) + B (trans).
// ---------------------------------------------------------------------------
#define GA_STR 40    // halves: 32 k + 8 pad
#define GB_STR 136   // halves: 128 n + 8 pad

template <int BM, int WM>
__global__ __launch_bounds__(256) void gemmh(
    const __half* __restrict__ W, const __half* __restrict__ X,
    const float* __restrict__ bias, float* __restrict__ Y, int K, int Mtot) {
    constexpr int NG = WM / 16;
    __shared__ __half Ah[2][BM * GA_STR];
    __shared__ __half Bh[2][32 * GB_STR];

    const int tid = threadIdx.x, lane = tid & 31, w = tid >> 5;
    const int g = lane >> 2, tg = lane & 3;
    const int wm0 = (w & 3) * WM, wn0 = (w >> 2) * 64;
    const int n0 = blockIdx.x * 128;
    const int m0 = blockIdx.y * BM;
    const int b  = blockIdx.z;
    const __half* Xb = X + (size_t)b * K * N_TOK;
    float* Yb = Y + (size_t)b * Mtot * N_TOK;

    const unsigned sA = (unsigned)__cvta_generic_to_shared(&Ah[0][0]);
    const unsigned sB = (unsigned)__cvta_generic_to_shared(&Bh[0][0]);
    // ldmatrix lane offsets (halves)
    const unsigned lpA = (((lane & 7) + ((lane >> 3) & 1) * 8) * GA_STR +
                          ((lane >> 4) & 1) * 8);
    const unsigned lpB = (((lane & 7) + ((lane >> 3) & 1) * 8) * GB_STR +
                          ((lane >> 4) & 1) * 8);

    float acc[NG][8][4] = {};

    auto issue = [&](int k0, int buf) {
#pragma unroll
        for (int e = tid; e < BM * 4; e += 256) {
            int m = e >> 2, kq = e & 3;
            cp16(sA + (buf * BM * GA_STR + m * GA_STR + kq * 8) * 2,
                 W + (size_t)(m0 + m) * K + k0 + kq * 8);
        }
#pragma unroll
        for (int e = tid; e < 512; e += 256) {
            int kk = e >> 4, nq = e & 15;
            cp16(sB + (buf * 32 * GB_STR + kk * GB_STR + nq * 8) * 2,
                 Xb + (size_t)(k0 + kk) * N_TOK + n0 + nq * 8);
        }
        CP_COMMIT;
    };

    issue(0, 0);
    const int nch = K >> 5;
    for (int ch = 0; ch < nch; ch++) {
        int buf = ch & 1;
        if (ch + 1 < nch) { issue((ch + 1) * 32, buf ^ 1); CP_WAIT(1); }
        else              { CP_WAIT(0); }
        __syncthreads();
        const unsigned aB = sA + buf * BM * GA_STR * 2;
        const unsigned bB = sB + buf * 32 * GB_STR * 2;
#pragma unroll
        for (int ks = 0; ks < 2; ks++) {
            unsigned a[NG][4];
#pragma unroll
            for (int s = 0; s < NG; s++)
                ldsm4(a[s], aB + ((wm0 + 16 * s) * GA_STR + ks * 16 + lpA) * 2);
#pragma unroll
            for (int j = 0; j < 4; j++) {
                unsigned bb[4];
                ldsm4t(bb, bB + (ks * 16 * GB_STR + wn0 + j * 16 + lpB) * 2);
#pragma unroll
                for (int s = 0; s < NG; s++) {
                    mma_f16(acc[s][2 * j],     a[s], &bb[0]);
                    mma_f16(acc[s][2 * j + 1], a[s], &bb[2]);
                }
            }
        }
        __syncthreads();
    }
#pragma unroll
    for (int s = 0; s < NG; s++) {
        int r0 = m0 + wm0 + 16 * s + g, r1 = r0 + 8;
        float bv0 = bias ? bias[r0] : 0.f;
        float bv1 = bias ? bias[r1] : 0.f;
#pragma unroll
        for (int nf = 0; nf < 8; nf++) {
            *(float2*)(Yb + (size_t)r0 * N_TOK + n0 + wn0 + nf * 8 + tg * 2) =
                make_float2(acc[s][nf][0] + bv0, acc[s][nf][1] + bv0);
            *(float2*)(Yb + (size_t)r1 * N_TOK + n0 + wn0 + nf * 8 + tg * 2) =
                make_float2(acc[s][nf][2] + bv1, acc[s][nf][3] + bv1);
        }
    }
}

// ---------------------------------------------------------------------------
// Row L2-norm inverse
// ---------------------------------------------------------------------------
__global__ void norm_k(const float* __restrict__ qkv, float* __restrict__ inv) {
    const int row = blockIdx.x;
    const int b = row >> 10, o = row & 1023;
    const float* p = qkv + ((size_t)b * 1536 + o) * N_TOK;
    float ss = 0.f;
    for (int i = threadIdx.x; i < N_TOK; i += 256) {
        float v = p[i];
        ss += v * v;
    }
#pragma unroll
    for (int off = 16; off; off >>= 1)
        ss += __shfl_xor_sync(0xffffffffu, ss, off);
    __shared__ float red[8];
    if ((threadIdx.x & 31) == 0) red[threadIdx.x >> 5] = ss;
    __syncthreads();
    if (threadIdx.x == 0) {
        float t = 0.f;
#pragma unroll
        for (int i = 0; i < 8; i++) t += red[i];
        inv[row] = 1.f / fmaxf(sqrtf(t), 1e-12f);
    }
}

// ---------------------------------------------------------------------------
// Convert q,k,v to fp16 attention layouts (unchanged, proven)
// ---------------------------------------------------------------------------
__global__ __launch_bounds__(256) void cvt_qkv(
    const float* __restrict__ qkv, const float* __restrict__ inv,
    __half* __restrict__ qh, __half* __restrict__ kh, __half* __restrict__ vh) {
    __shared__ float F[64 * 67];
    const int tid = threadIdx.x;
    const int t0 = blockIdx.x * 64;
    const int h = blockIdx.y, b = blockIdx.z;
    const int bh = b * 8 + h;
    const float* qsrc = qkv + ((size_t)b * 1536 + h * 64) * N_TOK;
    const float* ksrc = qsrc + (size_t)512 * N_TOK;
    const float* vsrc = qsrc + (size_t)1024 * N_TOK;
    const float* invq = inv + b * 1024 + h * 64;
    const float* invk = invq + 512;

    for (int e = tid; e < 1024; e += 256) {
        int d = e >> 4, m4 = e & 15;
        float4 t = *(const float4*)(vsrc + (size_t)d * N_TOK + t0 + m4 * 4);
        __half2* dst = (__half2*)(vh + ((size_t)bh * 64 + d) * N_TOK + t0 + m4 * 4);
        dst[0] = __floats2half2_rn(t.x, t.y);
        dst[1] = __floats2half2_rn(t.z, t.w);
    }

    for (int e = tid; e < 1024; e += 256) {
        int d = e >> 4, m4 = e & 15;
        float4 t = *(const float4*)(qsrc + (size_t)d * N_TOK + t0 + m4 * 4);
        float s = invq[d] * invk[d] * LOG2E;
        float* p = &F[d * 67 + m4 * 4];
        p[0] = t.x * s; p[1] = t.y * s; p[2] = t.z * s; p[3] = t.w * s;
    }
    __syncthreads();
    for (int e = tid; e < 512; e += 256) {
        int m = e >> 3, c = e & 7;
        __half2 o[4];
#pragma unroll
        for (int j = 0; j < 4; j++)
            o[j] = __floats2half2_rn(F[(8 * c + 2 * j) * 67 + m],
                                     F[(8 * c + 2 * j + 1) * 67 + m]);
        *(uint4*)(qh + ((size_t)bh * N_TOK + t0 + m) * 64 + 8 * c) = *(uint4*)o;
    }
    __syncthreads();

    for (int e = tid; e < 1024; e += 256) {
        int d = e >> 4, m4 = e & 15;
        float4 t = *(const float4*)(ksrc + (size_t)d * N_TOK + t0 + m4 * 4);
        float* p = &F[d * 67 + m4 * 4];
        p[0] = t.x; p[1] = t.y; p[2] = t.z; p[3] = t.w;
    }
    __syncthreads();
    for (int e = tid; e < 512; e += 256) {
        int m = e >> 3, c = e & 7;
        __half2 o[4];
#pragma unroll
        for (int j = 0; j < 4; j++)
            o[j] = __floats2half2_rn(F[(8 * c + 2 * j) * 67 + m],
                                     F[(8 * c + 2 * j + 1) * 67 + m]);
        *(uint4*)(kh + ((size_t)bh * N_TOK + t0 + m) * 64 + 8 * c) = *(uint4*)o;
    }
}

// ---------------------------------------------------------------------------
// Flash attention v7 (proven): fp16 k16 + ldmatrix + f16-accumulated S.
// Epilogue now writes fp16 att (feeds fp16 proj GEMM).
// ---------------------------------------------------------------------------
#define KT_STR 72
#define KV_STAGE (64 * KT_STR)
#define ATTN_SMEM (6 * KV_STAGE * 2)    // 55296 B

__global__ __launch_bounds__(256, 1) void attn7(
    const __half* __restrict__ qh, const __half* __restrict__ kh,
    const __half* __restrict__ vh, __half* __restrict__ out) {
    extern __shared__ __half smh[];

    const int tid = threadIdx.x, lane = tid & 31, w = tid >> 5;
    const int g = lane >> 2, tg = lane & 3;
    const int n0 = blockIdx.x * 256;
    const int bh = blockIdx.z * 8 + blockIdx.y;
    const int i0 = w * 32;

    const __half* qb = qh + (size_t)bh * N_TOK * 64;
    const __half* kb = kh + (size_t)bh * N_TOK * 64;
    const __half* vb = vh + (size_t)bh * 64 * N_TOK;

    const unsigned sBase = (unsigned)__cvta_generic_to_shared(smh);
    const unsigned lp = (((lane & 7) + ((lane >> 4) & 1) * 8) * KT_STR +
                         ((lane >> 3) & 1) * 8) * 2;

    auto issueKV = [&](int t0, int buf) {
#pragma unroll
        for (int e = tid; e < 512; e += 256) {
            int m = e >> 3, c = e & 7;
            cp16(sBase + (buf * KV_STAGE + m * KT_STR + c * 8) * 2,
                 kb + (size_t)(t0 + m) * 64 + c * 8);
            cp16(sBase + ((3 + buf) * KV_STAGE + m * KT_STR + c * 8) * 2,
                 vb + (size_t)m * N_TOK + t0 + c * 8);
        }
        CP_COMMIT;
    };

    issueKV(0, 0);
    issueKV(64, 1);
    issueKV(128, 2);

    unsigned qa[2][4][4];
#pragma unroll
    for (int grp = 0; grp < 2; grp++) {
#pragma unroll
        for (int kbk = 0; kbk < 4; kbk++) {
            const __half* r0p = qb + (size_t)(n0 + i0 + grp * 16 + g) * 64 + kbk * 16 + 2 * tg;
            const __half* r1p = r0p + 8 * 64;
            qa[grp][kbk][0] = *(const unsigned*)r0p;
            qa[grp][kbk][1] = *(const unsigned*)r1p;
            qa[grp][kbk][2] = *(const unsigned*)(r0p + 8);
            qa[grp][kbk][3] = *(const unsigned*)(r1p + 8);
        }
    }

    float O[2][8][4] = {};
    float l00 = 0.f, l01 = 0.f, l10 = 0.f, l11 = 0.f;

    for (int it = 0; it < 36; it++) {
        int buf = it % 3;
        CP_WAIT(2);
        __syncthreads();
        const unsigned kA = sBase + buf * KV_STAGE * 2 + lp;
        const unsigned vA = sBase + (3 + buf) * KV_STAGE * 2 + lp;

        unsigned S16[2][8][2];
#pragma unroll
        for (int grp = 0; grp < 2; grp++)
#pragma unroll
            for (int nf = 0; nf < 8; nf++) {
                S16[grp][nf][0] = 0u; S16[grp][nf][1] = 0u;
            }
#pragma unroll
        for (int kbk = 0; kbk < 4; kbk++) {
            unsigned kr[4][4];
#pragma unroll
            for (int q = 0; q < 4; q++)
                ldsm4(kr[q], kA + (q * 16 * KT_STR + kbk * 16) * 2);
#pragma unroll
            for (int q = 0; q < 4; q++) {
                mma_f16acc(S16[0][2 * q],     qa[0][kbk], &kr[q][0]);
                mma_f16acc(S16[0][2 * q + 1], qa[0][kbk], &kr[q][2]);
                mma_f16acc(S16[1][2 * q],     qa[1][kbk], &kr[q][0]);
                mma_f16acc(S16[1][2 * q + 1], qa[1][kbk], &kr[q][2]);
            }
        }

#pragma unroll
        for (int grp = 0; grp < 2; grp++)
#pragma unroll
            for (int nf = 0; nf < 8; nf++) {
                S16[grp][nf][0] = ex2h2(S16[grp][nf][0]);
                S16[grp][nf][1] = ex2h2(S16[grp][nf][1]);
            }
#pragma unroll
        for (int nf = 0; nf < 8; nf++) {
            float2 f;
            f = __half22float2(*(__half2*)&S16[0][nf][0]); l00 += f.x + f.y;
            f = __half22float2(*(__half2*)&S16[0][nf][1]); l01 += f.x + f.y;
            f = __half22float2(*(__half2*)&S16[1][nf][0]); l10 += f.x + f.y;
            f = __half22float2(*(__half2*)&S16[1][nf][1]); l11 += f.x + f.y;
        }

#pragma unroll
        for (int kk = 0; kk < 4; kk++) {
            unsigned vr[4][4];
#pragma unroll
            for (int q = 0; q < 4; q++)
                ldsm4(vr[q], vA + (q * 16 * KT_STR + kk * 16) * 2);
            unsigned pa0[4] = {S16[0][2 * kk][0], S16[0][2 * kk][1],
                              S16[0][2 * kk + 1][0], S16[0][2 * kk + 1][1]};
            unsigned pa1[4] = {S16[1][2 * kk][0], S16[1][2 * kk][1],
                              S16[1][2 * kk + 1][0], S16[1][2 * kk + 1][1]};
#pragma unroll
            for (int q = 0; q < 4; q++) {
                mma_f16(O[0][2 * q],     pa0, &vr[q][0]);
                mma_f16(O[0][2 * q + 1], pa0, &vr[q][2]);
                mma_f16(O[1][2 * q],     pa1, &vr[q][0]);
                mma_f16(O[1][2 * q + 1], pa1, &vr[q][2]);
            }
        }
        __syncthreads();
        if (it + 3 < 36) issueKV((it + 3) * 64, buf);
        else             CP_COMMIT;
    }

    l00 += __shfl_xor_sync(0xffffffffu, l00, 1);
    l00 += __shfl_xor_sync(0xffffffffu, l00, 2);
    l01 += __shfl_xor_sync(0xffffffffu, l01, 1);
    l01 += __shfl_xor_sync(0xffffffffu, l01, 2);
    l10 += __shfl_xor_sync(0xffffffffu, l10, 1);
    l10 += __shfl_xor_sync(0xffffffffu, l10, 2);
    l11 += __shfl_xor_sync(0xffffffffu, l11, 1);
    l11 += __shfl_xor_sync(0xffffffffu, l11, 2);
    float rl[2][2] = {{1.f / l00, 1.f / l01}, {1.f / l10, 1.f / l11}};

    // Epilogue: stage d-major f32 via smem, store fp16
    float* Os = (float*)smh;
    __half* ob = out + ((size_t)blockIdx.z * 512 + blockIdx.y * 64) * N_TOK;
#pragma unroll
    for (int pass = 0; pass < 2; pass++) {
        __syncthreads();
        if ((w >> 2) == pass) {
            int base = (w & 3) * 32;
#pragma unroll
            for (int grp = 0; grp < 2; grp++) {
                int ir0 = base + 16 * grp + g, ir1 = ir0 + 8;
#pragma unroll
                for (int nf = 0; nf < 8; nf++) {
                    int d0 = nf * 8 + 2 * tg;
                    Os[d0 * 136 + ir0]       = O[grp][nf][0] * rl[grp][0];
                    Os[(d0 + 1) * 136 + ir0] = O[grp][nf][1] * rl[grp][0];
                    Os[d0 * 136 + ir1]       = O[grp][nf][2] * rl[grp][1];
                    Os[(d0 + 1) * 136 + ir1] = O[grp][nf][3] * rl[grp][1];
                }
            }
        }
        __syncthreads();
        for (int e = tid; e < 2048; e += 256) {
            int d = e >> 5, i4 = e & 31;
            float4 t = *(const float4*)(&Os[d * 136 + i4 * 4]);
            __half2 h0 = __floats2half2_rn(t.x, t.y);
            __half2 h1 = __floats2half2_rn(t.z, t.w);
            *(uint2*)(ob + (size_t)d * N_TOK + n0 + pass * 128 + i4 * 4) =
                make_uint2(*(unsigned*)&h0, *(unsigned*)&h1);
        }
    }
}

// ---------------------------------------------------------------------------
extern "C" void kernel_launch(void* const* d_in, const int* in_sizes, int n_in,
                              void* d_out, int out_size) {
    (void)in_sizes; (void)n_in; (void)out_size;
    const float* x      = (const float*)d_in[0];
    const float* w_qkv  = (const float*)d_in[1];
    const float* w_proj = (const float*)d_in[2];
    const float* b_proj = (const float*)d_in[3];
    float* y = (float*)d_out;

    float *qkv_p, *inv_p;
    __half *xh_p, *w1h_p, *w2h_p, *qh_p, *kh_p, *vh_p, *atth_p;
    cudaGetSymbolAddress((void**)&qkv_p, g_qkv);
    cudaGetSymbolAddress((void**)&inv_p, g_inv);
    cudaGetSymbolAddress((void**)&xh_p, g_xh);
    cudaGetSymbolAddress((void**)&w1h_p, g_w1h);
    cudaGetSymbolAddress((void**)&w2h_p, g_w2h);
    cudaGetSymbolAddress((void**)&qh_p, g_qh);
    cudaGetSymbolAddress((void**)&kh_p, g_kh);
    cudaGetSymbolAddress((void**)&vh_p, g_vh);
    cudaGetSymbolAddress((void**)&atth_p, g_atth);

    cudaFuncSetAttribute(attn7, cudaFuncAttributeMaxDynamicSharedMemorySize,
                         ATTN_SMEM);

    // 0) convert x, weights to fp16
    cvt_in<<<4608, 256>>>(x, w_qkv, w_proj, xh_p, w1h_p, w2h_p);
    // 1) qkv = w_qkv @ x  (fp16 in, f32 out)
    gemmh<128, 32><<<dim3(18, 12, 2), 256>>>(w1h_p, xh_p, nullptr, qkv_p, 256, 1536);
    // 2) inverse L2 norms
    norm_k<<<2048, 256>>>(qkv_p, inv_p);
    // 3) convert to fp16 attention layouts
    cvt_qkv<<<dim3(36, 8, 2), 256>>>(qkv_p, inv_p, qh_p, kh_p, vh_p);
    // 4) flash attention fp16 -> fp16 att
    attn7<<<dim3(9, 8, 2), 256, ATTN_SMEM>>>(qh_p, kh_p, vh_p, atth_p);
    // 5) y = w_proj @ att + b_proj (fp16 in, f32 out)
    gemmh<64, 16><<<dim3(18, 4, 2), 256>>>(w2h_p, atth_p, b_proj, y, 512, 256);
}

// round 12
// speedup vs baseline: 2.1462x; 1.1322x over previous
#include <cuda_runtime.h>
#include <cuda_fp16.h>
#include <math.h>

#define N_TOK 2304
#define LOG2E 1.4426950408889634f

// Scratch (device globals: allocation-free per harness rules)
__device__ float  g_ssum[2 * 1024];            // sum of squares for q,k rows
__device__ float  g_inv[2 * 1024];             // inv L2 norms
__device__ __half g_xh[2u * 256u * 2304u];     // fp16 x
__device__ __half g_w1h[1536 * 256];           // fp16 w_qkv
__device__ __half g_w2h[256 * 512];            // fp16 w_proj
__device__ __half g_qkvh[2u * 1536u * 2304u];  // fp16 qkv, [b][ch][tok]
__device__ __half g_atth[2u * 512u * 2304u];   // fp16 attention output

// fp16 inputs, fp32 accumulator
__device__ __forceinline__ void mma_f16(float* d, const unsigned* a, const unsigned* b) {
    asm volatile(
        "mma.sync.aligned.m16n8k16.row.col.f32.f16.f16.f32 "
        "{%0,%1,%2,%3}, {%4,%5,%6,%7}, {%8,%9}, {%0,%1,%2,%3};\n"
        : "+f"(d[0]), "+f"(d[1]), "+f"(d[2]), "+f"(d[3])
        : "r"(a[0]), "r"(a[1]), "r"(a[2]), "r"(a[3]), "r"(b[0]), "r"(b[1]));
}
// fp16 inputs, fp16 accumulator (for S)
__device__ __forceinline__ void mma_f16acc(unsigned* d, const unsigned* a, const unsigned* b) {
    asm volatile(
        "mma.sync.aligned.m16n8k16.row.col.f16.f16.f16.f16 "
        "{%0,%1}, {%2,%3,%4,%5}, {%6,%7}, {%0,%1};\n"
        : "+r"(d[0]), "+r"(d[1])
        : "r"(a[0]), "r"(a[1]), "r"(a[2]), "r"(a[3]), "r"(b[0]), "r"(b[1]));
}
__device__ __forceinline__ void ldsm4(unsigned* r, unsigned addr) {
    asm volatile("ldmatrix.sync.aligned.m8n8.x4.shared.b16 {%0,%1,%2,%3}, [%4];"
                 : "=r"(r[0]), "=r"(r[1]), "=r"(r[2]), "=r"(r[3]) : "r"(addr));
}
__device__ __forceinline__ void ldsm4t(unsigned* r, unsigned addr) {
    asm volatile("ldmatrix.sync.aligned.m8n8.x4.trans.shared.b16 {%0,%1,%2,%3}, [%4];"
                 : "=r"(r[0]), "=r"(r[1]), "=r"(r[2]), "=r"(r[3]) : "r"(addr));
}
__device__ __forceinline__ unsigned ex2h2(unsigned x) {
    unsigned r;
    asm("ex2.approx.f16x2 %0, %1;" : "=r"(r) : "r"(x));
    return r;
}
__device__ __forceinline__ unsigned hmul2u(unsigned a, unsigned b) {
    unsigned r;
    asm("mul.rn.f16x2 %0, %1, %2;" : "=r"(r) : "r"(a), "r"(b));
    return r;
}
__device__ __forceinline__ void cp16(unsigned dst, const void* src) {
    asm volatile("cp.async.ca.shared.global [%0], [%1], 16;" :: "r"(dst), "l"(src));
}
#define CP_COMMIT asm volatile("cp.async.commit_group;")
#define CP_WAIT(n) asm volatile("cp.async.wait_group %0;" :: "n"(n))

// ---------------------------------------------------------------------------
// One-shot input conversion to fp16 (rn) + ssum zeroing
// ---------------------------------------------------------------------------
__global__ void cvt_in(const float* __restrict__ x, const float* __restrict__ w1,
                       const float* __restrict__ w2, __half* __restrict__ xh,
                       __half* __restrict__ w1h, __half* __restrict__ w2h,
                       float* __restrict__ ssum) {
    int i = blockIdx.x * 256 + threadIdx.x;
    if (i < 2 * 256 * 2304) xh[i] = __float2half_rn(x[i]);
    if (i < 1536 * 256)     w1h[i] = __float2half_rn(w1[i]);
    if (i < 256 * 512)      w2h[i] = __float2half_rn(w2[i]);
    if (i < 2048)           ssum[i] = 0.f;
}

__global__ void rsqk(const float* __restrict__ ssum, float* __restrict__ inv) {
    int i = blockIdx.x * 256 + threadIdx.x;
    if (i < 2048) inv[i] = 1.f / fmaxf(sqrtf(ssum[i]), 1e-12f);
}

// ---------------------------------------------------------------------------
// fp16 qkv GEMM: Yh[b][m][n] = sum_k W[m][k]*X[b][k][n], fp16 out,
// + sum-of-squares atomics for q,k rows (m < 1024). BM=128, K=256.
// ---------------------------------------------------------------------------
#define GA_STR 40
#define GB_STR 136

__global__ __launch_bounds__(256) void gemmqkv(
    const __half* __restrict__ W, const __half* __restrict__ X,
    __half* __restrict__ Yh, float* __restrict__ ssum) {
    __shared__ __half Ah[2][128 * GA_STR];
    __shared__ __half Bh[2][32 * GB_STR];

    const int tid = threadIdx.x, lane = tid & 31, w = tid >> 5;
    const int g = lane >> 2, tg = lane & 3;
    const int wm0 = (w & 3) * 32, wn0 = (w >> 2) * 64;
    const int n0 = blockIdx.x * 128;
    const int m0 = blockIdx.y * 128;
    const int b  = blockIdx.z;
    const bool doss = (m0 < 1024);
    const __half* Xb = X + (size_t)b * 256 * N_TOK;

    const unsigned sA = (unsigned)__cvta_generic_to_shared(&Ah[0][0]);
    const unsigned sB = (unsigned)__cvta_generic_to_shared(&Bh[0][0]);
    const unsigned lpA = (((lane & 7) + ((lane >> 3) & 1) * 8) * GA_STR +
                          ((lane >> 4) & 1) * 8);
    const unsigned lpB = (((lane & 7) + ((lane >> 3) & 1) * 8) * GB_STR +
                          ((lane >> 4) & 1) * 8);

    float acc[2][8][4] = {};

    auto issue = [&](int k0, int buf) {
#pragma unroll
        for (int e = tid; e < 512; e += 256) {
            int m = e >> 2, kq = e & 3;
            cp16(sA + (buf * 128 * GA_STR + m * GA_STR + kq * 8) * 2,
                 W + (size_t)(m0 + m) * 256 + k0 + kq * 8);
        }
#pragma unroll
        for (int e = tid; e < 512; e += 256) {
            int kk = e >> 4, nq = e & 15;
            cp16(sB + (buf * 32 * GB_STR + kk * GB_STR + nq * 8) * 2,
                 Xb + (size_t)(k0 + kk) * N_TOK + n0 + nq * 8);
        }
        CP_COMMIT;
    };

    issue(0, 0);
    for (int ch = 0; ch < 8; ch++) {
        int buf = ch & 1;
        if (ch + 1 < 8) { issue((ch + 1) * 32, buf ^ 1); CP_WAIT(1); }
        else            { CP_WAIT(0); }
        __syncthreads();
        const unsigned aB = sA + buf * 128 * GA_STR * 2;
        const unsigned bB = sB + buf * 32 * GB_STR * 2;
#pragma unroll
        for (int ks = 0; ks < 2; ks++) {
            unsigned a[2][4];
#pragma unroll
            for (int s = 0; s < 2; s++)
                ldsm4(a[s], aB + ((wm0 + 16 * s) * GA_STR + ks * 16 + lpA) * 2);
#pragma unroll
            for (int j = 0; j < 4; j++) {
                unsigned bb[4];
                ldsm4t(bb, bB + (ks * 16 * GB_STR + wn0 + j * 16 + lpB) * 2);
#pragma unroll
                for (int s = 0; s < 2; s++) {
                    mma_f16(acc[s][2 * j],     a[s], &bb[0]);
                    mma_f16(acc[s][2 * j + 1], a[s], &bb[2]);
                }
            }
        }
        __syncthreads();
    }
#pragma unroll
    for (int s = 0; s < 2; s++) {
        int r0 = m0 + wm0 + 16 * s + g, r1 = r0 + 8;
        float ss0 = 0.f, ss1 = 0.f;
#pragma unroll
        for (int nf = 0; nf < 8; nf++) {
            float a0 = acc[s][nf][0], a1 = acc[s][nf][1];
            float a2 = acc[s][nf][2], a3 = acc[s][nf][3];
            __half2 h0 = __floats2half2_rn(a0, a1);
            __half2 h1 = __floats2half2_rn(a2, a3);
            *(unsigned*)(Yh + (size_t)(b * 1536 + r0) * N_TOK + n0 + wn0 + nf * 8 + tg * 2) =
                *(unsigned*)&h0;
            *(unsigned*)(Yh + (size_t)(b * 1536 + r1) * N_TOK + n0 + wn0 + nf * 8 + tg * 2) =
                *(unsigned*)&h1;
            ss0 += a0 * a0 + a1 * a1;
            ss1 += a2 * a2 + a3 * a3;
        }
        if (doss) {
            ss0 += __shfl_xor_sync(0xffffffffu, ss0, 1);
            ss0 += __shfl_xor_sync(0xffffffffu, ss0, 2);
            ss1 += __shfl_xor_sync(0xffffffffu, ss1, 1);
            ss1 += __shfl_xor_sync(0xffffffffu, ss1, 2);
            if (tg == 0) {
                atomicAdd(&ssum[b * 1024 + r0], ss0);
                atomicAdd(&ssum[b * 1024 + r1], ss1);
            }
        }
    }
}

// ---------------------------------------------------------------------------
// fp16 GEMM for proj (unchanged, proven): f32 out + bias
// ---------------------------------------------------------------------------
template <int BM, int WM>
__global__ __launch_bounds__(256) void gemmh(
    const __half* __restrict__ W, const __half* __restrict__ X,
    const float* __restrict__ bias, float* __restrict__ Y, int K, int Mtot) {
    constexpr int NG = WM / 16;
    __shared__ __half Ah[2][BM * GA_STR];
    __shared__ __half Bh[2][32 * GB_STR];

    const int tid = threadIdx.x, lane = tid & 31, w = tid >> 5;
    const int g = lane >> 2, tg = lane & 3;
    const int wm0 = (w & 3) * WM, wn0 = (w >> 2) * 64;
    const int n0 = blockIdx.x * 128;
    const int m0 = blockIdx.y * BM;
    const int b  = blockIdx.z;
    const __half* Xb = X + (size_t)b * K * N_TOK;
    float* Yb = Y + (size_t)b * Mtot * N_TOK;

    const unsigned sA = (unsigned)__cvta_generic_to_shared(&Ah[0][0]);
    const unsigned sB = (unsigned)__cvta_generic_to_shared(&Bh[0][0]);
    const unsigned lpA = (((lane & 7) + ((lane >> 3) & 1) * 8) * GA_STR +
                          ((lane >> 4) & 1) * 8);
    const unsigned lpB = (((lane & 7) + ((lane >> 3) & 1) * 8) * GB_STR +
                          ((lane >> 4) & 1) * 8);

    float acc[NG][8][4] = {};

    auto issue = [&](int k0, int buf) {
#pragma unroll
        for (int e = tid; e < BM * 4; e += 256) {
            int m = e >> 2, kq = e & 3;
            cp16(sA + (buf * BM * GA_STR + m * GA_STR + kq * 8) * 2,
                 W + (size_t)(m0 + m) * K + k0 + kq * 8);
        }
#pragma unroll
        for (int e = tid; e < 512; e += 256) {
            int kk = e >> 4, nq = e & 15;
            cp16(sB + (buf * 32 * GB_STR + kk * GB_STR + nq * 8) * 2,
                 Xb + (size_t)(k0 + kk) * N_TOK + n0 + nq * 8);
        }
        CP_COMMIT;
    };

    issue(0, 0);
    const int nch = K >> 5;
    for (int ch = 0; ch < nch; ch++) {
        int buf = ch & 1;
        if (ch + 1 < nch) { issue((ch + 1) * 32, buf ^ 1); CP_WAIT(1); }
        else              { CP_WAIT(0); }
        __syncthreads();
        const unsigned aB = sA + buf * BM * GA_STR * 2;
        const unsigned bB = sB + buf * 32 * GB_STR * 2;
#pragma unroll
        for (int ks = 0; ks < 2; ks++) {
            unsigned a[NG][4];
#pragma unroll
            for (int s = 0; s < NG; s++)
                ldsm4(a[s], aB + ((wm0 + 16 * s) * GA_STR + ks * 16 + lpA) * 2);
#pragma unroll
            for (int j = 0; j < 4; j++) {
                unsigned bb[4];
                ldsm4t(bb, bB + (ks * 16 * GB_STR + wn0 + j * 16 + lpB) * 2);
#pragma unroll
                for (int s = 0; s < NG; s++) {
                    mma_f16(acc[s][2 * j],     a[s], &bb[0]);
                    mma_f16(acc[s][2 * j + 1], a[s], &bb[2]);
                }
            }
        }
        __syncthreads();
    }
#pragma unroll
    for (int s = 0; s < NG; s++) {
        int r0 = m0 + wm0 + 16 * s + g, r1 = r0 + 8;
        float bv0 = bias ? bias[r0] : 0.f;
        float bv1 = bias ? bias[r1] : 0.f;
#pragma unroll
        for (int nf = 0; nf < 8; nf++) {
            *(float2*)(Yb + (size_t)r0 * N_TOK + n0 + wn0 + nf * 8 + tg * 2) =
                make_float2(acc[s][nf][0] + bv0, acc[s][nf][1] + bv0);
            *(float2*)(Yb + (size_t)r1 * N_TOK + n0 + wn0 + nf * 8 + tg * 2) =
                make_float2(acc[s][nf][2] + bv1, acc[s][nf][3] + bv1);
        }
    }
}

// ---------------------------------------------------------------------------
// Flash attention v8: all sources [bh][d][tok] fp16 straight from qkv GEMM.
// Q staged once (cp.async) + ldsm4t A-frags + post-hoist per-d scaling.
// K via ldsm4t, V via ldsm4. Bounded softmax, 3-stage KV pipeline.
// Smem halves: Q[64][264] | K[3][64][72] | V[3][64][72]
// ---------------------------------------------------------------------------
#define QS_STR 264
#define KT_STR 72
#define KV_STAGE (64 * KT_STR)
#define Q_SMEM (64 * QS_STR)
#define ATTN_SMEM ((Q_SMEM + 6 * KV_STAGE) * 2)   // 89088 B

__global__ __launch_bounds__(256, 1) void attn8(
    const __half* __restrict__ qkvh, const float* __restrict__ inv,
    __half* __restrict__ out) {
    extern __shared__ __half smh[];

    const int tid = threadIdx.x, lane = tid & 31, w = tid >> 5;
    const int g = lane >> 2, tg = lane & 3;
    const int n0 = blockIdx.x * 256;
    const int i0 = w * 32;

    const __half* qb = qkvh + (size_t)(blockIdx.z * 1536 + blockIdx.y * 64) * N_TOK;
    const __half* kb = qb + (size_t)512 * N_TOK;
    const __half* vb = qb + (size_t)1024 * N_TOK;
    const float* invq = inv + blockIdx.z * 1024 + blockIdx.y * 64;
    const float* invk = invq + 512;

    const unsigned sBase = (unsigned)__cvta_generic_to_shared(smh);

    auto issueKV = [&](int t0, int buf) {
#pragma unroll
        for (int e = tid; e < 512; e += 256) {
            int d = e >> 3, c = e & 7;
            cp16(sBase + (Q_SMEM + buf * KV_STAGE + d * KT_STR + c * 8) * 2,
                 kb + (size_t)d * N_TOK + t0 + c * 8);
            cp16(sBase + (Q_SMEM + (3 + buf) * KV_STAGE + d * KT_STR + c * 8) * 2,
                 vb + (size_t)d * N_TOK + t0 + c * 8);
        }
        CP_COMMIT;
    };

    // Q stage (one-time): 64 d x 256 tok
    {
#pragma unroll
        for (int e = tid; e < 2048; e += 256) {
            int d = e >> 5, c = e & 31;
            cp16(sBase + (d * QS_STR + c * 8) * 2, qb + (size_t)d * N_TOK + n0 + c * 8);
        }
        CP_COMMIT;
    }
    issueKV(0, 0);
    issueKV(64, 1);
    issueKV(128, 2);

    // Per-lane scale half2s: sc[kbk][hi] covers d = kbk*16 + 2tg (+1), +8
    unsigned sc[4][2];
#pragma unroll
    for (int kbk = 0; kbk < 4; kbk++) {
        int d0 = kbk * 16 + 2 * tg;
        __half2 s0 = __floats2half2_rn(invq[d0] * invk[d0] * LOG2E,
                                       invq[d0 + 1] * invk[d0 + 1] * LOG2E);
        __half2 s1 = __floats2half2_rn(invq[d0 + 8] * invk[d0 + 8] * LOG2E,
                                       invq[d0 + 9] * invk[d0 + 9] * LOG2E);
        sc[kbk][0] = *(unsigned*)&s0;
        sc[kbk][1] = *(unsigned*)&s1;
    }

    CP_WAIT(3);          // Q complete
    __syncthreads();

    // Hoist Q A-fragments via ldmatrix.trans, then apply per-d scale
    const int dlA = (lane & 7) + ((lane >> 4) & 1) * 8;   // bit4 -> d+8
    const int toA = ((lane >> 3) & 1) * 8;                // bit3 -> tok+8
    unsigned qa[2][4][4];
#pragma unroll
    for (int grp = 0; grp < 2; grp++) {
#pragma unroll
        for (int kbk = 0; kbk < 4; kbk++) {
            ldsm4t(qa[grp][kbk],
                   sBase + ((kbk * 16 + dlA) * QS_STR + i0 + grp * 16 + toA) * 2);
            qa[grp][kbk][0] = hmul2u(qa[grp][kbk][0], sc[kbk][0]);
            qa[grp][kbk][1] = hmul2u(qa[grp][kbk][1], sc[kbk][0]);
            qa[grp][kbk][2] = hmul2u(qa[grp][kbk][2], sc[kbk][1]);
            qa[grp][kbk][3] = hmul2u(qa[grp][kbk][3], sc[kbk][1]);
        }
    }

    const int dlB = (lane & 7) + ((lane >> 3) & 1) * 8;   // K: bit3 -> d+8
    const int toB = ((lane >> 4) & 1) * 8;                //    bit4 -> tok+8
    const unsigned lpV = (((lane & 7) + ((lane >> 4) & 1) * 8) * KT_STR +
                          ((lane >> 3) & 1) * 8) * 2;

    float O[2][8][4] = {};
    float l00 = 0.f, l01 = 0.f, l10 = 0.f, l11 = 0.f;

    for (int it = 0; it < 36; it++) {
        int buf = it % 3;
        CP_WAIT(2);
        __syncthreads();
        const unsigned kA = sBase + (Q_SMEM + buf * KV_STAGE) * 2;
        const unsigned vA = sBase + (Q_SMEM + (3 + buf) * KV_STAGE) * 2 + lpV;

        unsigned S16[2][8][2];
#pragma unroll
        for (int grp = 0; grp < 2; grp++)
#pragma unroll
            for (int nf = 0; nf < 8; nf++) {
                S16[grp][nf][0] = 0u; S16[grp][nf][1] = 0u;
            }
#pragma unroll
        for (int kbk = 0; kbk < 4; kbk++) {
            unsigned kr[4][4];
#pragma unroll
            for (int q = 0; q < 4; q++)
                ldsm4t(kr[q], kA + ((kbk * 16 + dlB) * KT_STR + q * 16 + toB) * 2);
#pragma unroll
            for (int q = 0; q < 4; q++) {
                mma_f16acc(S16[0][2 * q],     qa[0][kbk], &kr[q][0]);
                mma_f16acc(S16[0][2 * q + 1], qa[0][kbk], &kr[q][2]);
                mma_f16acc(S16[1][2 * q],     qa[1][kbk], &kr[q][0]);
                mma_f16acc(S16[1][2 * q + 1], qa[1][kbk], &kr[q][2]);
            }
        }

#pragma unroll
        for (int grp = 0; grp < 2; grp++)
#pragma unroll
            for (int nf = 0; nf < 8; nf++) {
                S16[grp][nf][0] = ex2h2(S16[grp][nf][0]);
                S16[grp][nf][1] = ex2h2(S16[grp][nf][1]);
            }
#pragma unroll
        for (int nf = 0; nf < 8; nf++) {
            float2 f;
            f = __half22float2(*(__half2*)&S16[0][nf][0]); l00 += f.x + f.y;
            f = __half22float2(*(__half2*)&S16[0][nf][1]); l01 += f.x + f.y;
            f = __half22float2(*(__half2*)&S16[1][nf][0]); l10 += f.x + f.y;
            f = __half22float2(*(__half2*)&S16[1][nf][1]); l11 += f.x + f.y;
        }

#pragma unroll
        for (int kk = 0; kk < 4; kk++) {
            unsigned vr[4][4];
#pragma unroll
            for (int q = 0; q < 4; q++)
                ldsm4(vr[q], vA + (q * 16 * KT_STR + kk * 16) * 2);
            unsigned pa0[4] = {S16[0][2 * kk][0], S16[0][2 * kk][1],
                              S16[0][2 * kk + 1][0], S16[0][2 * kk + 1][1]};
            unsigned pa1[4] = {S16[1][2 * kk][0], S16[1][2 * kk][1],
                              S16[1][2 * kk + 1][0], S16[1][2 * kk + 1][1]};
#pragma unroll
            for (int q = 0; q < 4; q++) {
                mma_f16(O[0][2 * q],     pa0, &vr[q][0]);
                mma_f16(O[0][2 * q + 1], pa0, &vr[q][2]);
                mma_f16(O[1][2 * q],     pa1, &vr[q][0]);
                mma_f16(O[1][2 * q + 1], pa1, &vr[q][2]);
            }
        }
        __syncthreads();
        if (it + 3 < 36) issueKV((it + 3) * 64, buf);
        else             CP_COMMIT;
    }

    l00 += __shfl_xor_sync(0xffffffffu, l00, 1);
    l00 += __shfl_xor_sync(0xffffffffu, l00, 2);
    l01 += __shfl_xor_sync(0xffffffffu, l01, 1);
    l01 += __shfl_xor_sync(0xffffffffu, l01, 2);
    l10 += __shfl_xor_sync(0xffffffffu, l10, 1);
    l10 += __shfl_xor_sync(0xffffffffu, l10, 2);
    l11 += __shfl_xor_sync(0xffffffffu, l11, 1);
    l11 += __shfl_xor_sync(0xffffffffu, l11, 2);
    float rl[2][2] = {{1.f / l00, 1.f / l01}, {1.f / l10, 1.f / l11}};

    // Epilogue: stage d-major f32 via smem, store fp16
    float* Os = (float*)smh;
    __half* ob = out + ((size_t)blockIdx.z * 512 + blockIdx.y * 64) * N_TOK;
#pragma unroll
    for (int pass = 0; pass < 2; pass++) {
        __syncthreads();
        if ((w >> 2) == pass) {
            int base = (w & 3) * 32;
#pragma unroll
            for (int grp = 0; grp < 2; grp++) {
                int ir0 = base + 16 * grp + g, ir1 = ir0 + 8;
#pragma unroll
                for (int nf = 0; nf < 8; nf++) {
                    int d0 = nf * 8 + 2 * tg;
                    Os[d0 * 136 + ir0]       = O[grp][nf][0] * rl[grp][0];
                    Os[(d0 + 1) * 136 + ir0] = O[grp][nf][1] * rl[grp][0];
                    Os[d0 * 136 + ir1]       = O[grp][nf][2] * rl[grp][1];
                    Os[(d0 + 1) * 136 + ir1] = O[grp][nf][3] * rl[grp][1];
                }
            }
        }
        __syncthreads();
        for (int e = tid; e < 2048; e += 256) {
            int d = e >> 5, i4 = e & 31;
            float4 t = *(const float4*)(&Os[d * 136 + i4 * 4]);
            __half2 h0 = __floats2half2_rn(t.x, t.y);
            __half2 h1 = __floats2half2_rn(t.z, t.w);
            *(uint2*)(ob + (size_t)d * N_TOK + n0 + pass * 128 + i4 * 4) =
                make_uint2(*(unsigned*)&h0, *(unsigned*)&h1);
        }
    }
}

// ---------------------------------------------------------------------------
extern "C" void kernel_launch(void* const* d_in, const int* in_sizes, int n_in,
                              void* d_out, int out_size) {
    (void)in_sizes; (void)n_in; (void)out_size;
    const float* x      = (const float*)d_in[0];
    const float* w_qkv  = (const float*)d_in[1];
    const float* w_proj = (const float*)d_in[2];
    const float* b_proj = (const float*)d_in[3];
    float* y = (float*)d_out;

    float *ssum_p, *inv_p;
    __half *xh_p, *w1h_p, *w2h_p, *qkvh_p, *atth_p;
    cudaGetSymbolAddress((void**)&ssum_p, g_ssum);
    cudaGetSymbolAddress((void**)&inv_p, g_inv);
    cudaGetSymbolAddress((void**)&xh_p, g_xh);
    cudaGetSymbolAddress((void**)&w1h_p, g_w1h);
    cudaGetSymbolAddress((void**)&w2h_p, g_w2h);
    cudaGetSymbolAddress((void**)&qkvh_p, g_qkvh);
    cudaGetSymbolAddress((void**)&atth_p, g_atth);

    cudaFuncSetAttribute(attn8, cudaFuncAttributeMaxDynamicSharedMemorySize,
                         ATTN_SMEM);

    // 0) convert inputs to fp16, zero ssum
    cvt_in<<<4608, 256>>>(x, w_qkv, w_proj, xh_p, w1h_p, w2h_p, ssum_p);
    // 1) qkv = w_qkv @ x -> fp16 qkv + q/k sum-of-squares
    gemmqkv<<<dim3(18, 12, 2), 256>>>(w1h_p, xh_p, qkvh_p, ssum_p);
    // 2) inv norms
    rsqk<<<8, 256>>>(ssum_p, inv_p);
    // 3) flash attention (fp16 end-to-end)
    attn8<<<dim3(9, 8, 2), 256, ATTN_SMEM>>>(qkvh_p, inv_p, atth_p);
    // 4) y = w_proj @ att + b_proj
    gemmh<64, 16><<<dim3(18, 4, 2), 256>>>(w2h_p, atth_p, b_proj, y, 512, 256);
}